// round 5
// baseline (speedup 1.0000x reference)
#include <cuda_runtime.h>
#include <cuda_bf16.h>
#include <cstdint>

#define NB 256
#define NS 512
#define ND 256
#define NA 128
#define TS 128
#define NTILE (NS / TS)     // 4
#define KC 32
#define NCHUNK (ND / KC)    // 8
#define MH 64               // rows via HMMA (warps 0-3)
#define ASTR 40             // bf16 row stride (80B, ldmatrix conflict-free)
#define XSTR 36             // fp32 row stride (144B, 16B aligned)

// ---- scratch (allocation-free rule: device globals) ----
__device__ float g_part[NB * NTILE * ND];
__device__ float g_esum[NB * NTILE];
__device__ __nv_bfloat16 g_wt_hi[NA * ND];   // [n][k] K-major
__device__ __nv_bfloat16 g_wt_lo[NA * ND];

// ---- smem layout (bytes) ----
#define OFF_ES   0
#define OFF_BSM  512
#define OFF_USM  1024
#define OFF_RED  1536
#define OFF_AH(b) (2048 + (b) * 10240)              // 64*40*2 = 5120 each
#define OFF_AL(b) (OFF_AH(b) + 5120)
#define OFF_XF(b) (22528 + (b) * 9216)              // 64*36*4 = 9216
#define OFF_MAT   OFF_XF(0)                          // 64*17*4 = 4352, reused post-loop
#define SMEM_TOTAL 40960

#define LDSM4(r, addr) \
    asm volatile("ldmatrix.sync.aligned.m8n8.x4.shared.b16 {%0,%1,%2,%3}, [%4];" \
        : "=r"((r)[0]), "=r"((r)[1]), "=r"((r)[2]), "=r"((r)[3]) : "r"(addr))

#define MMA16816(d, a, b0, b1) \
    asm volatile("mma.sync.aligned.m16n8k16.row.col.f32.bf16.bf16.f32 " \
        "{%0,%1,%2,%3},{%4,%5,%6,%7},{%8,%9},{%0,%1,%2,%3};" \
        : "+f"((d)[0]), "+f"((d)[1]), "+f"((d)[2]), "+f"((d)[3]) \
        : "r"((a)[0]), "r"((a)[1]), "r"((a)[2]), "r"((a)[3]), "r"(b0), "r"(b1))

__device__ __forceinline__ void cp16(char* dst, const char* src) {
    unsigned saddr = (unsigned)__cvta_generic_to_shared(dst);
    asm volatile("cp.async.cg.shared.global [%0], [%1], 16;\n" :: "r"(saddr), "l"(src));
}
__device__ __forceinline__ void cp_commit() { asm volatile("cp.async.commit_group;\n"); }
template<int N> __device__ __forceinline__ void cp_wait() {
    asm volatile("cp.async.wait_group %0;\n" :: "n"(N));
}
__device__ __forceinline__ uint32_t pack_bf2(float a, float b) {
    __nv_bfloat162 t = __halves2bfloat162(__float2bfloat16(a), __float2bfloat16(b));
    return *(uint32_t*)&t;
}
__device__ __forceinline__ unsigned long long pack2(float lo, float hi) {
    unsigned long long r;
    asm("mov.b64 %0, {%1, %2};" : "=l"(r) : "f"(lo), "f"(hi));
    return r;
}
__device__ __forceinline__ void unpack2(unsigned long long v, float& lo, float& hi) {
    asm("mov.b64 {%0, %1}, %2;" : "=f"(lo), "=f"(hi) : "l"(v));
}
__device__ __forceinline__ void ffma2(unsigned long long& acc, unsigned long long a, unsigned long long b) {
    asm("fma.rn.f32x2 %0, %1, %2, %0;" : "+l"(acc) : "l"(a), "l"(b));
}
__device__ __forceinline__ float fast_tanh(float x) {
    float e = __expf(2.0f * x);
    return 1.0f - __fdividef(2.0f, e + 1.0f);
}

// ---------------------------------------------------------------------------
__global__ void __launch_bounds__(256) wprep_kernel(const float* __restrict__ W) {
    int idx = blockIdx.x * 256 + threadIdx.x;
    if (idx < ND * NA) {
        int k = idx >> 7;
        int n = idx & (NA - 1);
        float w = W[idx];
        __nv_bfloat16 h = __float2bfloat16(w);
        g_wt_hi[n * ND + k] = h;
        g_wt_lo[n * ND + k] = __float2bfloat16(w - __bfloat162float(h));
    }
}

// ---------------------------------------------------------------------------
// Hybrid: warps 0-3 HMMA (rows 0-63, bf16 3-pass), warps 4-7 FFMA2 fp32
// (rows 64-127).  W read direct from global (L2-hot); only x-fp32 via cp.async.
// ---------------------------------------------------------------------------
__global__ void __launch_bounds__(256, 2) scores_kernel(
    const float* __restrict__ x, const float* __restrict__ W,
    const float* __restrict__ bias, const float* __restrict__ u)
{
    extern __shared__ char smem[];
    const uint32_t smb = (uint32_t)__cvta_generic_to_shared(smem);

    const int b    = blockIdx.y;
    const int tile = blockIdx.x;
    const int s0   = tile * TS;
    const int tid  = threadIdx.x;
    const int w    = tid >> 5;
    const int l    = tid & 31;

    float* es  = (float*)(smem + OFF_ES);
    float* bsm = (float*)(smem + OFF_BSM);
    float* usm = (float*)(smem + OFF_USM);
    float* red = (float*)(smem + OFF_RED);

    if (tid < NA) { bsm[tid] = bias[tid]; usm[tid] = u[tid]; }
    if (tid < TS) red[tid] = 0.0f;

    const float* xb = x + ((size_t)b * NS + s0) * ND;

    // ===== HMMA-side helpers (tid < 128) =====
    const int xrow  = tid >> 1;     // 0..63
    const int xcolh = tid & 1;
    float4 st[4];
    auto load_x = [&](int c) {
        const float* p = xb + (size_t)xrow * ND + c * KC + xcolh * 16;
#pragma unroll
        for (int i = 0; i < 4; i++) st[i] = ((const float4*)p)[i];
    };
    auto sts_x = [&](int buf) {
        uint32_t hv[8], lv[8];
#pragma unroll
        for (int i = 0; i < 4; i++) {
            float vs[4] = { st[i].x, st[i].y, st[i].z, st[i].w };
            float ls[4];
#pragma unroll
            for (int j = 0; j < 4; j++) {
                __nv_bfloat16 h = __float2bfloat16(vs[j]);
                ls[j] = vs[j] - __bfloat162float(h);
            }
            hv[2*i]   = pack_bf2(vs[0], vs[1]);
            hv[2*i+1] = pack_bf2(vs[2], vs[3]);
            lv[2*i]   = pack_bf2(ls[0], ls[1]);
            lv[2*i+1] = pack_bf2(ls[2], ls[3]);
        }
        int off = xrow * (ASTR * 2) + xcolh * 32;
        *(uint4*)(smem + OFF_AH(buf) + off)      = make_uint4(hv[0], hv[1], hv[2], hv[3]);
        *(uint4*)(smem + OFF_AH(buf) + off + 16) = make_uint4(hv[4], hv[5], hv[6], hv[7]);
        *(uint4*)(smem + OFF_AL(buf) + off)      = make_uint4(lv[0], lv[1], lv[2], lv[3]);
        *(uint4*)(smem + OFF_AL(buf) + off + 16) = make_uint4(lv[4], lv[5], lv[6], lv[7]);
    };
    auto issue_xf = [&](int c, int buf) {          // rows 64-127 fp32, tid<128
#pragma unroll
        for (int it = 0; it < 4; it++) {
            int idx = tid + it * 128;              // 0..511
            int row = idx >> 3;
            int seg = idx & 7;
            cp16(smem + OFF_XF(buf) + row * (XSTR * 4) + seg * 16,
                 (const char*)(xb + (size_t)(MH + row) * ND + c * KC + seg * 4));
        }
        cp_commit();
    };

    // HMMA state (warps 0-3): warp tile 32M x 64N
    const int wm = w >> 1, wn = w & 1;
    float acc[2][8][4];
    // FFMA2 state (warps 4-7): thread tile 8x8 over rows 64-127
    const int wgtid = tid & 127;
    const int ty = wgtid >> 4, tx = wgtid & 15;
    unsigned long long acc2[8][4];

    if (w < 4) {
#pragma unroll
        for (int m = 0; m < 2; m++)
#pragma unroll
            for (int nf = 0; nf < 8; nf++)
#pragma unroll
                for (int e = 0; e < 4; e++) acc[m][nf][e] = 0.0f;
    } else {
#pragma unroll
        for (int i = 0; i < 8; i++)
#pragma unroll
            for (int p = 0; p < 4; p++) acc2[i][p] = 0ull;
    }

    const uint32_t lane_off = (uint32_t)((l & 15) * (ASTR * 2) + (l >> 4) * 16);
    // B-fragment lane mapping (m16n8k16 col-major B): n = l>>2, k = 2*(l&3)
    const int bn_lane = wn * 64 + (l >> 2);
    const int bk_lane = (l & 3) * 2;

    // ---- prologue ----
    if (tid < 128) { load_x(0); issue_xf(0, 0); sts_x(0); }
    else           { cp_commit(); }                    // keep group counts aligned

#pragma unroll 1
    for (int c = 0; c < NCHUNK; c++) {
        const int buf = c & 1;
        if (tid < 128) {
            if (c < NCHUNK - 1) { issue_xf(c + 1, buf ^ 1); load_x(c + 1); }
            else cp_commit();
        } else cp_commit();
        cp_wait<1>();
        __syncthreads();

        if (w < 4) {
            // ===== HMMA rows 0-63 =====
            const uint32_t ah_base = smb + OFF_AH(buf) + (uint32_t)(wm * 32) * (ASTR * 2) + lane_off;
            const uint32_t al_base = smb + OFF_AL(buf) + (uint32_t)(wm * 32) * (ASTR * 2) + lane_off;
#pragma unroll
            for (int kk = 0; kk < KC; kk += 16) {
                uint32_t ah[2][4], al[2][4];
#pragma unroll
                for (int m = 0; m < 2; m++) {
                    LDSM4(ah[m], ah_base + m * 16 * (ASTR * 2) + kk * 2);
                    LDSM4(al[m], al_base + m * 16 * (ASTR * 2) + kk * 2);
                }
                const int kbase = c * KC + kk + bk_lane;
#pragma unroll
                for (int np = 0; np < 4; np++) {
                    uint32_t bh[4], bl[4];
#pragma unroll
                    for (int sn = 0; sn < 2; sn++)
#pragma unroll
                        for (int kh = 0; kh < 2; kh++) {
                            size_t idx = (size_t)(bn_lane + np * 16 + sn * 8) * ND + kbase + kh * 8;
                            bh[kh * 2 + sn] = *(const uint32_t*)(g_wt_hi + idx);
                            bl[kh * 2 + sn] = *(const uint32_t*)(g_wt_lo + idx);
                        }
#pragma unroll
                    for (int m = 0; m < 2; m++)
#pragma unroll
                        for (int sn = 0; sn < 2; sn++) {
                            float* d = acc[m][np * 2 + sn];
                            uint32_t h0 = sn ? bh[1] : bh[0], h1 = sn ? bh[3] : bh[2];
                            uint32_t l0 = sn ? bl[1] : bl[0], l1 = sn ? bl[3] : bl[2];
                            MMA16816(d, ah[m], h0, h1);
                            MMA16816(d, ah[m], l0, l1);
                            MMA16816(d, al[m], h0, h1);
                        }
                }
            }
            if (c < NCHUNK - 1) sts_x(buf ^ 1);
        } else {
            // ===== FFMA2 rows 64-127 (exact fp32), W direct from global =====
            const float* xc = (const float*)(smem + OFF_XF(buf));
#pragma unroll
            for (int kk = 0; kk < KC; kk += 2) {
                float2 ax[8];
#pragma unroll
                for (int i = 0; i < 8; i++)
                    ax[i] = *(const float2*)(xc + (ty * 8 + i) * XSTR + kk);
                unsigned long long wp[2][4];
#pragma unroll
                for (int sub = 0; sub < 2; sub++) {
                    const float* wr = W + (size_t)(c * KC + kk + sub) * NA + 2 * tx;
#pragma unroll
                    for (int p = 0; p < 4; p++)
                        wp[sub][p] = *(const unsigned long long*)(wr + 32 * p);
                }
#pragma unroll
                for (int sub = 0; sub < 2; sub++)
#pragma unroll
                    for (int i = 0; i < 8; i++) {
                        float a = sub ? ax[i].y : ax[i].x;
                        unsigned long long ap = pack2(a, a);
#pragma unroll
                        for (int p = 0; p < 4; p++) ffma2(acc2[i][p], ap, wp[sub][p]);
                    }
            }
        }
        __syncthreads();
    }

    // ---- epilogues ----
    if (w < 4) {
        const int g = l >> 2, tig = l & 3;
#pragma unroll
        for (int m = 0; m < 2; m++) {
            float pA = 0.0f, pB = 0.0f;
#pragma unroll
            for (int nf = 0; nf < 8; nf++)
#pragma unroll
                for (int e = 0; e < 2; e++) {
                    int col = wn * 64 + nf * 8 + 2 * tig + e;
                    pA += fast_tanh(acc[m][nf][e]     + bsm[col]) * usm[col];
                    pB += fast_tanh(acc[m][nf][2 + e] + bsm[col]) * usm[col];
                }
            pA += __shfl_xor_sync(0xffffffffu, pA, 1);
            pA += __shfl_xor_sync(0xffffffffu, pA, 2);
            pB += __shfl_xor_sync(0xffffffffu, pB, 1);
            pB += __shfl_xor_sync(0xffffffffu, pB, 2);
            if (tig == 0) {
                int row = wm * 32 + m * 16 + g;
                atomicAdd(&red[row], pA);          // 2 contributors/row
                atomicAdd(&red[row + 8], pB);
            }
        }
    } else {
        float* mat = (float*)(smem + OFF_MAT);     // 64 x 17
#pragma unroll
        for (int i = 0; i < 8; i++) {
            float partial = 0.0f;
#pragma unroll
            for (int p = 0; p < 4; p++) {
                float lo, hi; unpack2(acc2[i][p], lo, hi);
                int c0 = 2 * tx + 32 * p;
                partial += fast_tanh(lo + bsm[c0])     * usm[c0];
                partial += fast_tanh(hi + bsm[c0 + 1]) * usm[c0 + 1];
            }
            mat[(ty * 8 + i) * 17 + tx] = partial;
        }
    }
    __syncthreads();
    if (tid < 64) {
        const float* mat = (const float*)(smem + OFF_MAT);
        float lg = 0.0f;
#pragma unroll
        for (int j = 0; j < 16; j++) lg += mat[tid * 17 + j];
        red[MH + tid] = lg;
    }
    __syncthreads();
    if (tid < TS) es[tid] = expf(red[tid]);        // faithful: no max-subtraction
    __syncthreads();

    // tile exp-sum (deterministic tree)
    if (tid < 64) red[tid] = es[tid] + es[tid + 64];
    __syncthreads();
    if (tid < 32) {
        float v = red[tid] + red[tid + 32];
#pragma unroll
        for (int off = 16; off > 0; off >>= 1)
            v += __shfl_down_sync(0xffffffffu, v, off);
        if (tid == 0) g_esum[b * NTILE + tile] = v;
    }

    // weighted partial sum over tile rows (x L2-hot)
    float a0 = 0.f, a1 = 0.f, a2 = 0.f, a3 = 0.f;
#pragma unroll 4
    for (int s = 0; s < TS; s += 4) {
        a0 += es[s + 0] * xb[(size_t)(s + 0) * ND + tid];
        a1 += es[s + 1] * xb[(size_t)(s + 1) * ND + tid];
        a2 += es[s + 2] * xb[(size_t)(s + 2) * ND + tid];
        a3 += es[s + 3] * xb[(size_t)(s + 3) * ND + tid];
    }
    g_part[((size_t)b * NTILE + tile) * ND + tid] = (a0 + a1) + (a2 + a3);
}

// ---------------------------------------------------------------------------
__global__ void __launch_bounds__(256) finish_kernel(float* __restrict__ out)
{
    const int b = blockIdx.x;
    const int tid = threadIdx.x;
    float s = 0.f;
#pragma unroll
    for (int t = 0; t < NTILE; t++) s += g_esum[b * NTILE + t];
    const float inv = 1.0f / (s + 1e-8f);
    float v = 0.f;
#pragma unroll
    for (int t = 0; t < NTILE; t++) v += g_part[((size_t)b * NTILE + t) * ND + tid];
    out[b * ND + tid] = v * inv;
}

extern "C" void kernel_launch(void* const* d_in, const int* in_sizes, int n_in,
                              void* d_out, int out_size) {
    const float* x    = (const float*)d_in[0];
    const float* W    = (const float*)d_in[1];
    const float* bias = (const float*)d_in[2];
    const float* u    = (const float*)d_in[3];
    float* out        = (float*)d_out;

    cudaFuncSetAttribute(scores_kernel, cudaFuncAttributeMaxDynamicSharedMemorySize, SMEM_TOTAL);

    wprep_kernel<<<(ND * NA + 255) / 256, 256>>>(W);
    scores_kernel<<<dim3(NTILE, NB), 256, SMEM_TOTAL>>>(x, W, bias, u);
    finish_kernel<<<NB, 256>>>(out);
}

// round 6
// speedup vs baseline: 2.1727x; 2.1727x over previous
#include <cuda_runtime.h>
#include <cuda_bf16.h>
#include <cstdint>

#define NB 256
#define NS 512
#define ND 256
#define NA 128
#define TS 128
#define NTILE (NS / TS)     // 4
#define KC 32
#define NCHUNK (ND / KC)    // 8
#define ASTR2 80            // bf16 tile row stride in BYTES (conflict-free ldmatrix)

// ---- scratch (allocation-free rule: device globals) ----
__device__ float g_part[NB * NTILE * ND];
__device__ float g_esum[NB * NTILE];
__device__ __nv_bfloat16 g_wt_hi[NA * ND];   // [n][k] K-major
__device__ __nv_bfloat16 g_wt_lo[NA * ND];

// ---- smem layout (bytes) ----
#define OFF_ES   0
#define OFF_BSM  512
#define OFF_USM  1024
#define OFF_RED  1536
#define OFF_AH(b) (2048 + (b) * 10240)            // 64 rows * 80B
#define OFF_AL(b) (OFF_AH(b) + 5120)
#define OFF_BH(b) (22528 + (b) * 20480)           // 128 rows * 80B
#define OFF_BL(b) (OFF_BH(b) + 10240)
#define OFF_XF(b) (63488 + (b) * 8192)            // 64 rows * 128B fp32
#define OFF_WF(b) (79872 + (b) * 16384)           // 32 rows * 512B fp32
#define OFF_MAT   OFF_XF(0)                        // 64*17*4 = 4352, reused post-loop
#define SMEM_TOTAL 112640

#define LDSM4(r, addr) \
    asm volatile("ldmatrix.sync.aligned.m8n8.x4.shared.b16 {%0,%1,%2,%3}, [%4];" \
        : "=r"((r)[0]), "=r"((r)[1]), "=r"((r)[2]), "=r"((r)[3]) : "r"(addr))

#define MMA16816(d, a, b0, b1) \
    asm volatile("mma.sync.aligned.m16n8k16.row.col.f32.bf16.bf16.f32 " \
        "{%0,%1,%2,%3},{%4,%5,%6,%7},{%8,%9},{%0,%1,%2,%3};" \
        : "+f"((d)[0]), "+f"((d)[1]), "+f"((d)[2]), "+f"((d)[3]) \
        : "r"((a)[0]), "r"((a)[1]), "r"((a)[2]), "r"((a)[3]), "r"(b0), "r"(b1))

__device__ __forceinline__ void cp16(char* dst, const char* src) {
    unsigned saddr = (unsigned)__cvta_generic_to_shared(dst);
    asm volatile("cp.async.cg.shared.global [%0], [%1], 16;\n" :: "r"(saddr), "l"(src));
}
__device__ __forceinline__ void cp_commit() { asm volatile("cp.async.commit_group;\n"); }
template<int N> __device__ __forceinline__ void cp_wait() {
    asm volatile("cp.async.wait_group %0;\n" :: "n"(N));
}
__device__ __forceinline__ uint32_t pack_bf2(float a, float b) {
    __nv_bfloat162 t = __halves2bfloat162(__float2bfloat16(a), __float2bfloat16(b));
    return *(uint32_t*)&t;
}
__device__ __forceinline__ unsigned long long pack2(float lo, float hi) {
    unsigned long long r;
    asm("mov.b64 %0, {%1, %2};" : "=l"(r) : "f"(lo), "f"(hi));
    return r;
}
__device__ __forceinline__ void unpack2(unsigned long long v, float& lo, float& hi) {
    asm("mov.b64 {%0, %1}, %2;" : "=f"(lo), "=f"(hi) : "l"(v));
}
__device__ __forceinline__ void ffma2(unsigned long long& acc, unsigned long long a, unsigned long long b) {
    asm("fma.rn.f32x2 %0, %1, %2, %0;" : "+l"(acc) : "l"(a), "l"(b));
}
__device__ __forceinline__ float fast_tanh(float x) {
    float e = __expf(2.0f * x);
    return 1.0f - __fdividef(2.0f, e + 1.0f);
}

// ---------------------------------------------------------------------------
__global__ void __launch_bounds__(256) wprep_kernel(const float* __restrict__ W) {
    int idx = blockIdx.x * 256 + threadIdx.x;
    if (idx < ND * NA) {
        int k = idx >> 7;
        int n = idx & (NA - 1);
        float w = W[idx];
        __nv_bfloat16 h = __float2bfloat16(w);
        g_wt_hi[n * ND + k] = h;
        g_wt_lo[n * ND + k] = __float2bfloat16(w - __bfloat162float(h));
    }
}

// ---------------------------------------------------------------------------
// Dual-pipe: every warp does HMMA (rows 0-63, bf16 3-pass) AND FFMA2
// (rows 64-127, exact fp32) per chunk.  All operands smem-staged.
// ---------------------------------------------------------------------------
__global__ void __launch_bounds__(256, 2) scores_kernel(
    const float* __restrict__ x, const float* __restrict__ W,
    const float* __restrict__ bias, const float* __restrict__ u)
{
    extern __shared__ char smem[];
    const uint32_t smb = (uint32_t)__cvta_generic_to_shared(smem);

    const int b    = blockIdx.y;
    const int tile = blockIdx.x;
    const int s0   = tile * TS;
    const int tid  = threadIdx.x;
    const int w    = tid >> 5;
    const int l    = tid & 31;

    float* es  = (float*)(smem + OFF_ES);
    float* bsm = (float*)(smem + OFF_BSM);
    float* usm = (float*)(smem + OFF_USM);
    float* red = (float*)(smem + OFF_RED);

    if (tid < NA) { bsm[tid] = bias[tid]; usm[tid] = u[tid]; }
    if (tid < TS) red[tid] = 0.0f;

    const float* xb = x + ((size_t)b * NS + s0) * ND;

    // ---- A convert staging: rows 0-63, 4 threads/row ----
    const int xrow = tid >> 2;          // 0..63
    const int xseg = tid & 3;           // 8-float segment
    float4 st[2];
    auto load_x = [&](int c) {
        const float* p = xb + (size_t)xrow * ND + c * KC + xseg * 8;
        st[0] = ((const float4*)p)[0];
        st[1] = ((const float4*)p)[1];
    };
    auto sts_x = [&](int buf) {
        uint32_t hv[4], lv[4];
#pragma unroll
        for (int i = 0; i < 2; i++) {
            float vs[4] = { st[i].x, st[i].y, st[i].z, st[i].w };
            float ls[4];
#pragma unroll
            for (int j = 0; j < 4; j++) {
                __nv_bfloat16 h = __float2bfloat16(vs[j]);
                ls[j] = vs[j] - __bfloat162float(h);
            }
            hv[2*i]   = pack_bf2(vs[0], vs[1]);
            hv[2*i+1] = pack_bf2(vs[2], vs[3]);
            lv[2*i]   = pack_bf2(ls[0], ls[1]);
            lv[2*i+1] = pack_bf2(ls[2], ls[3]);
        }
        int off = xrow * ASTR2 + xseg * 16;
        *(uint4*)(smem + OFF_AH(buf) + off) = make_uint4(hv[0], hv[1], hv[2], hv[3]);
        *(uint4*)(smem + OFF_AL(buf) + off) = make_uint4(lv[0], lv[1], lv[2], lv[3]);
    };
    // ---- cp.async staging: xf (rows 64-127 fp32), B bf16 hi/lo, W fp32 ----
    auto issue_async = [&](int c, int buf) {
#pragma unroll
        for (int it = 0; it < 2; it++) {            // xf: 512 cp16
            int idx = tid + it * 256;
            int row = idx >> 3, seg = idx & 7;
            cp16(smem + OFF_XF(buf) + row * 128 + seg * 16,
                 (const char*)(xb + (size_t)(64 + row) * ND + c * KC) + seg * 16);
        }
#pragma unroll
        for (int it = 0; it < 4; it++) {            // B: 1024 cp16
            int idx = tid + it * 256;
            int h = idx >> 9, rem = idx & 511;
            int n = rem >> 2, s = rem & 3;
            const char* src = (const char*)((h ? g_wt_lo : g_wt_hi) + (size_t)n * ND + c * KC) + s * 16;
            cp16(smem + (h ? OFF_BL(buf) : OFF_BH(buf)) + n * ASTR2 + s * 16, src);
        }
#pragma unroll
        for (int it = 0; it < 4; it++) {            // wf: 1024 cp16
            int idx = tid + it * 256;
            int k = idx >> 5, seg = idx & 31;
            cp16(smem + OFF_WF(buf) + k * 512 + seg * 16,
                 (const char*)(W + (size_t)(c * KC + k) * NA) + seg * 16);
        }
        cp_commit();
    };

    // HMMA state: warp tile 16M x 64N  (m = w>>1 over rows 0-63, wn = w&1)
    const int wm = w >> 1, wn = w & 1;
    float acc[8][4];
#pragma unroll
    for (int nf = 0; nf < 8; nf++)
#pragma unroll
        for (int e = 0; e < 4; e++) acc[nf][e] = 0.0f;

    // FFMA2 state: thread tile 4 rows x 8 cols over rows 64-127
    const int ty = tid >> 4, tx = tid & 15;
    unsigned long long acc2[4][4];
#pragma unroll
    for (int i = 0; i < 4; i++)
#pragma unroll
        for (int p = 0; p < 4; p++) acc2[i][p] = 0ull;

    const uint32_t lane_off = (uint32_t)((l & 15) * ASTR2 + (l >> 4) * 16);

    // ---- prologue ----
    load_x(0);
    issue_async(0, 0);
    sts_x(0);

#pragma unroll 1
    for (int c = 0; c < NCHUNK; c++) {
        const int buf = c & 1;
        if (c < NCHUNK - 1) { issue_async(c + 1, buf ^ 1); load_x(c + 1); cp_wait<1>(); }
        else cp_wait<0>();
        __syncthreads();

        // ===== HMMA rows 0-63 =====
        {
            const uint32_t ah_base = smb + OFF_AH(buf) + (uint32_t)(wm * 16) * ASTR2 + lane_off;
            const uint32_t al_base = smb + OFF_AL(buf) + (uint32_t)(wm * 16) * ASTR2 + lane_off;
            const uint32_t bh_base = smb + OFF_BH(buf) + (uint32_t)(wn * 64) * ASTR2 + lane_off;
            const uint32_t bl_base = smb + OFF_BL(buf) + (uint32_t)(wn * 64) * ASTR2 + lane_off;
#pragma unroll
            for (int kk = 0; kk < KC; kk += 16) {
                uint32_t ah[4], al[4];
                LDSM4(ah, ah_base + kk * 2);
                LDSM4(al, al_base + kk * 2);
#pragma unroll
                for (int np = 0; np < 4; np++) {
                    uint32_t bh[4], bl[4];
                    LDSM4(bh, bh_base + np * 16 * ASTR2 + kk * 2);
                    LDSM4(bl, bl_base + np * 16 * ASTR2 + kk * 2);
#pragma unroll
                    for (int sn = 0; sn < 2; sn++) {
                        float* d = acc[np * 2 + sn];
                        uint32_t h0 = sn ? bh[1] : bh[0], h1 = sn ? bh[3] : bh[2];
                        uint32_t l0 = sn ? bl[1] : bl[0], l1 = sn ? bl[3] : bl[2];
                        MMA16816(d, ah, h0, h1);
                        MMA16816(d, ah, l0, l1);
                        MMA16816(d, al, h0, h1);
                    }
                }
            }
        }
        // ===== FFMA2 rows 64-127 (exact fp32) =====
        {
            const float* xc = (const float*)(smem + OFF_XF(buf));
            const float* wc = (const float*)(smem + OFF_WF(buf));
#pragma unroll
            for (int kk = 0; kk < KC; kk += 2) {
                float2 ax[4];
#pragma unroll
                for (int i = 0; i < 4; i++)
                    ax[i] = *(const float2*)(xc + (ty * 4 + i) * 32 + kk);
#pragma unroll
                for (int sub = 0; sub < 2; sub++) {
                    const float* wr = wc + (kk + sub) * NA + 2 * tx;
                    unsigned long long wp[4];
#pragma unroll
                    for (int p = 0; p < 4; p++)
                        wp[p] = *(const unsigned long long*)(wr + 32 * p);
#pragma unroll
                    for (int i = 0; i < 4; i++) {
                        float a = sub ? ax[i].y : ax[i].x;
                        unsigned long long ap = pack2(a, a);
#pragma unroll
                        for (int p = 0; p < 4; p++) ffma2(acc2[i][p], ap, wp[p]);
                    }
                }
            }
        }
        if (c < NCHUNK - 1) sts_x(buf ^ 1);
        __syncthreads();
    }

    // ---- epilogue: HMMA rows 0-63 ----
    {
        const int g = l >> 2, tig = l & 3;
        float pA = 0.0f, pB = 0.0f;
#pragma unroll
        for (int nf = 0; nf < 8; nf++)
#pragma unroll
            for (int e = 0; e < 2; e++) {
                int col = wn * 64 + nf * 8 + 2 * tig + e;
                pA += fast_tanh(acc[nf][e]     + bsm[col]) * usm[col];
                pB += fast_tanh(acc[nf][2 + e] + bsm[col]) * usm[col];
            }
        pA += __shfl_xor_sync(0xffffffffu, pA, 1);
        pA += __shfl_xor_sync(0xffffffffu, pA, 2);
        pB += __shfl_xor_sync(0xffffffffu, pB, 1);
        pB += __shfl_xor_sync(0xffffffffu, pB, 2);
        if (tig == 0) {
            atomicAdd(&red[wm * 16 + g], pA);       // 2 contributors/row (wn=0,1)
            atomicAdd(&red[wm * 16 + 8 + g], pB);
        }
    }
    // ---- epilogue: FFMA rows 64-127 ----
    {
        float* mat = (float*)(smem + OFF_MAT);      // 64 x 17
#pragma unroll
        for (int i = 0; i < 4; i++) {
            float partial = 0.0f;
#pragma unroll
            for (int p = 0; p < 4; p++) {
                float lo, hi; unpack2(acc2[i][p], lo, hi);
                int c0 = 2 * tx + 32 * p;
                partial += fast_tanh(lo + bsm[c0])     * usm[c0];
                partial += fast_tanh(hi + bsm[c0 + 1]) * usm[c0 + 1];
            }
            mat[(ty * 4 + i) * 17 + tx] = partial;
        }
    }
    __syncthreads();
    if (tid < 64) {
        const float* mat = (const float*)(smem + OFF_MAT);
        float lg = 0.0f;
#pragma unroll
        for (int j = 0; j < 16; j++) lg += mat[tid * 17 + j];
        red[64 + tid] = lg;
    }
    __syncthreads();
    if (tid < TS) es[tid] = expf(red[tid]);         // faithful: no max-subtraction
    __syncthreads();

    // tile exp-sum (deterministic tree)
    if (tid < 64) red[tid] = es[tid] + es[tid + 64];
    __syncthreads();
    if (tid < 32) {
        float v = red[tid] + red[tid + 32];
#pragma unroll
        for (int off = 16; off > 0; off >>= 1)
            v += __shfl_down_sync(0xffffffffu, v, off);
        if (tid == 0) g_esum[b * NTILE + tile] = v;
    }

    // weighted partial sum over tile rows (x L2-hot)
    float a0 = 0.f, a1 = 0.f, a2 = 0.f, a3 = 0.f;
#pragma unroll 4
    for (int s = 0; s < TS; s += 4) {
        a0 += es[s + 0] * xb[(size_t)(s + 0) * ND + tid];
        a1 += es[s + 1] * xb[(size_t)(s + 1) * ND + tid];
        a2 += es[s + 2] * xb[(size_t)(s + 2) * ND + tid];
        a3 += es[s + 3] * xb[(size_t)(s + 3) * ND + tid];
    }
    g_part[((size_t)b * NTILE + tile) * ND + tid] = (a0 + a1) + (a2 + a3);
}

// ---------------------------------------------------------------------------
__global__ void __launch_bounds__(256) finish_kernel(float* __restrict__ out)
{
    const int b = blockIdx.x;
    const int tid = threadIdx.x;
    float s = 0.f;
#pragma unroll
    for (int t = 0; t < NTILE; t++) s += g_esum[b * NTILE + t];
    const float inv = 1.0f / (s + 1e-8f);
    float v = 0.f;
#pragma unroll
    for (int t = 0; t < NTILE; t++) v += g_part[((size_t)b * NTILE + t) * ND + tid];
    out[b * ND + tid] = v * inv;
}

extern "C" void kernel_launch(void* const* d_in, const int* in_sizes, int n_in,
                              void* d_out, int out_size) {
    const float* x    = (const float*)d_in[0];
    const float* W    = (const float*)d_in[1];
    const float* bias = (const float*)d_in[2];
    const float* u    = (const float*)d_in[3];
    float* out        = (float*)d_out;

    cudaFuncSetAttribute(scores_kernel, cudaFuncAttributeMaxDynamicSharedMemorySize, SMEM_TOTAL);

    wprep_kernel<<<(ND * NA + 255) / 256, 256>>>(W);
    scores_kernel<<<dim3(NTILE, NB), 256, SMEM_TOTAL>>>(x, W, bias, u);
    finish_kernel<<<NB, 256>>>(out);
}

// round 7
// speedup vs baseline: 2.2122x; 1.0182x over previous
#include <cuda_runtime.h>
#include <cuda_bf16.h>
#include <cstdint>

#define NB 256
#define NS 512
#define ND 256
#define NA 128
#define TS 128
#define NTILE (NS / TS)     // 4
#define KC 32
#define NCHUNK (ND / KC)    // 8
#define ASTR 40             // H-path bf16 row stride (elems) = 80B
#define XSTR 36             // F-path fp32 row stride (floats)

// ---- scratch (allocation-free rule: device globals) ----
__device__ float g_part[NB * NTILE * ND];
__device__ float g_esum[NB * NTILE];
__device__ __nv_bfloat16 g_wt_hi[NA * ND];   // [n][k] K-major
__device__ __nv_bfloat16 g_wt_lo[NA * ND];

// ---- H-path smem layout (bytes), as round-4 (verified) ----
#define H_ES    0
#define H_BSM   512
#define H_USM   1024
#define H_RED   1536
#define H_TILES 2048
#define HTILE_B (TS * ASTR * 2)          // 10240
#define H_AH(buf) (H_TILES + (buf) * 4 * HTILE_B + 0 * HTILE_B)
#define H_AL(buf) (H_TILES + (buf) * 4 * HTILE_B + 1 * HTILE_B)
#define H_BH(buf) (H_TILES + (buf) * 4 * HTILE_B + 2 * HTILE_B)
#define H_BL(buf) (H_TILES + (buf) * 4 * HTILE_B + 3 * HTILE_B)
#define SMEM_TOTAL (H_TILES + 8 * HTILE_B)   // 83968

// ---- F-path smem layout (bytes), as round-2 (verified) ----
#define F_XS(buf) ((buf) * 18432)            // 128 * 36 floats
#define F_WS(buf) (36864 + (buf) * 16384)    // 32 * 128 floats
#define F_BSM  69632
#define F_USM  70144
#define F_ES   70656                          // ends 71168 <= 83968

#define LDSM4(r, addr) \
    asm volatile("ldmatrix.sync.aligned.m8n8.x4.shared.b16 {%0,%1,%2,%3}, [%4];" \
        : "=r"((r)[0]), "=r"((r)[1]), "=r"((r)[2]), "=r"((r)[3]) : "r"(addr))

#define MMA16816(d, a, b0, b1) \
    asm volatile("mma.sync.aligned.m16n8k16.row.col.f32.bf16.bf16.f32 " \
        "{%0,%1,%2,%3},{%4,%5,%6,%7},{%8,%9},{%0,%1,%2,%3};" \
        : "+f"((d)[0]), "+f"((d)[1]), "+f"((d)[2]), "+f"((d)[3]) \
        : "r"((a)[0]), "r"((a)[1]), "r"((a)[2]), "r"((a)[3]), "r"(b0), "r"(b1))

__device__ __forceinline__ void cp16(char* dst, const char* src) {
    unsigned saddr = (unsigned)__cvta_generic_to_shared(dst);
    asm volatile("cp.async.cg.shared.global [%0], [%1], 16;\n" :: "r"(saddr), "l"(src));
}
__device__ __forceinline__ void cp_commit() { asm volatile("cp.async.commit_group;\n"); }
template<int N> __device__ __forceinline__ void cp_wait() {
    asm volatile("cp.async.wait_group %0;\n" :: "n"(N));
}
__device__ __forceinline__ uint32_t pack_bf2(float a, float b) {
    __nv_bfloat162 t = __halves2bfloat162(__float2bfloat16(a), __float2bfloat16(b));
    return *(uint32_t*)&t;
}
__device__ __forceinline__ unsigned long long pack2(float lo, float hi) {
    unsigned long long r;
    asm("mov.b64 %0, {%1, %2};" : "=l"(r) : "f"(lo), "f"(hi));
    return r;
}
__device__ __forceinline__ void unpack2(unsigned long long v, float& lo, float& hi) {
    asm("mov.b64 {%0, %1}, %2;" : "=f"(lo), "=f"(hi) : "l"(v));
}
__device__ __forceinline__ void ffma2(unsigned long long& acc, unsigned long long a, unsigned long long b) {
    asm("fma.rn.f32x2 %0, %1, %2, %0;" : "+l"(acc) : "l"(a), "l"(b));
}
__device__ __forceinline__ float fast_tanh(float x) {
    float e = __expf(2.0f * x);
    return 1.0f - __fdividef(2.0f, e + 1.0f);
}

// ---------------------------------------------------------------------------
__global__ void __launch_bounds__(256) wprep_kernel(const float* __restrict__ W) {
    int idx = blockIdx.x * 256 + threadIdx.x;
    if (idx < ND * NA) {
        int k = idx >> 7;
        int n = idx & (NA - 1);
        float w = W[idx];
        __nv_bfloat16 h = __float2bfloat16(w);
        g_wt_hi[n * ND + k] = h;
        g_wt_lo[n * ND + k] = __float2bfloat16(w - __bfloat162float(h));
    }
}

// ---------------------------------------------------------------------------
// Heterogeneous grid: bid%3 != 2 -> HMMA CTA (round-4 engine, tensor pipe),
// bid%3 == 2 -> FFMA2 CTA (round-2 engine, fma pipe).  683:341 split matches
// measured per-unit costs (24.6k vs 45.8k cyc); SM co-residency (occ 2)
// overlaps the two pipes.
// ---------------------------------------------------------------------------
__global__ void __launch_bounds__(256, 2) scores_kernel(
    const float* __restrict__ x, const float* __restrict__ W,
    const float* __restrict__ bias, const float* __restrict__ u)
{
    extern __shared__ char smem[];
    const uint32_t smb = (uint32_t)__cvta_generic_to_shared(smem);

    const int bid  = blockIdx.x;
    const int tile = bid & 3;
    const int b    = bid >> 2;
    const int tid  = threadIdx.x;
    const float* xb = x + ((size_t)b * NS + tile * TS) * ND;

    if ((bid % 3) != 2) {
        // ===================== H path: 3-pass bf16 HMMA =====================
        const int w = tid >> 5, l = tid & 31;
        const int wm = w >> 1, wn = w & 1;
        float* es  = (float*)(smem + H_ES);
        float* bsm = (float*)(smem + H_BSM);
        float* usm = (float*)(smem + H_USM);
        float* red = (float*)(smem + H_RED);

        if (tid < NA) { bsm[tid] = bias[tid]; usm[tid] = u[tid]; }
        if (tid < TS) red[tid] = 0.0f;

        const int xrow = tid >> 1, xcolh = tid & 1;
        float4 st[4];
        auto load_x = [&](int c) {
            const float* p = xb + (size_t)xrow * ND + c * KC + xcolh * 16;
#pragma unroll
            for (int i = 0; i < 4; i++) st[i] = ((const float4*)p)[i];
        };
        auto sts_x = [&](int buf) {
            uint32_t hv[8], lv[8];
#pragma unroll
            for (int i = 0; i < 4; i++) {
                float vs[4] = { st[i].x, st[i].y, st[i].z, st[i].w };
                float ls[4];
#pragma unroll
                for (int j = 0; j < 4; j++) {
                    __nv_bfloat16 h = __float2bfloat16(vs[j]);
                    ls[j] = vs[j] - __bfloat162float(h);
                }
                hv[2*i]   = pack_bf2(vs[0], vs[1]);
                hv[2*i+1] = pack_bf2(vs[2], vs[3]);
                lv[2*i]   = pack_bf2(ls[0], ls[1]);
                lv[2*i+1] = pack_bf2(ls[2], ls[3]);
            }
            int off = xrow * (ASTR * 2) + xcolh * 32;
            *(uint4*)(smem + H_AH(buf) + off)      = make_uint4(hv[0], hv[1], hv[2], hv[3]);
            *(uint4*)(smem + H_AH(buf) + off + 16) = make_uint4(hv[4], hv[5], hv[6], hv[7]);
            *(uint4*)(smem + H_AL(buf) + off)      = make_uint4(lv[0], lv[1], lv[2], lv[3]);
            *(uint4*)(smem + H_AL(buf) + off + 16) = make_uint4(lv[4], lv[5], lv[6], lv[7]);
        };
        auto cp_w = [&](int c, int buf) {
#pragma unroll
            for (int it = 0; it < 4; it++) {
                int idx = tid + it * 256;
                int h = idx >> 9, rem = idx & 511;
                int n = rem >> 2, s = rem & 3;
                const char* src = (const char*)(h ? g_wt_lo : g_wt_hi) + (size_t)n * (ND * 2) + c * (KC * 2) + s * 16;
                cp16(smem + (h ? H_BL(buf) : H_BH(buf)) + n * (ASTR * 2) + s * 16, src);
            }
            cp_commit();
        };

        float acc[2][8][4];
#pragma unroll
        for (int m = 0; m < 2; m++)
#pragma unroll
            for (int nf = 0; nf < 8; nf++)
#pragma unroll
                for (int e = 0; e < 4; e++) acc[m][nf][e] = 0.0f;

        const uint32_t lane_off = (uint32_t)((l & 15) * (ASTR * 2) + (l >> 4) * 16);

        load_x(0);
        cp_w(0, 0);
        sts_x(0);

#pragma unroll 1
        for (int c = 0; c < NCHUNK; c++) {
            const int buf = c & 1;
            if (c < NCHUNK - 1) { cp_w(c + 1, buf ^ 1); load_x(c + 1); cp_wait<1>(); }
            else cp_wait<0>();
            __syncthreads();

            const uint32_t ah_base = smb + H_AH(buf) + (uint32_t)(wm * 32) * (ASTR * 2) + lane_off;
            const uint32_t al_base = smb + H_AL(buf) + (uint32_t)(wm * 32) * (ASTR * 2) + lane_off;
            const uint32_t bh_base = smb + H_BH(buf) + (uint32_t)(wn * 64) * (ASTR * 2) + lane_off;
            const uint32_t bl_base = smb + H_BL(buf) + (uint32_t)(wn * 64) * (ASTR * 2) + lane_off;

#pragma unroll
            for (int kk = 0; kk < KC; kk += 16) {
                uint32_t ah[2][4], al[2][4];
#pragma unroll
                for (int m = 0; m < 2; m++) {
                    LDSM4(ah[m], ah_base + m * 16 * (ASTR * 2) + kk * 2);
                    LDSM4(al[m], al_base + m * 16 * (ASTR * 2) + kk * 2);
                }
#pragma unroll
                for (int np = 0; np < 4; np++) {
                    uint32_t bh[4], bl[4];
                    LDSM4(bh, bh_base + np * 16 * (ASTR * 2) + kk * 2);
                    LDSM4(bl, bl_base + np * 16 * (ASTR * 2) + kk * 2);
#pragma unroll
                    for (int m = 0; m < 2; m++)
#pragma unroll
                        for (int sn = 0; sn < 2; sn++) {
                            float* d = acc[m][np * 2 + sn];
                            uint32_t h0 = sn ? bh[1] : bh[0], h1 = sn ? bh[3] : bh[2];
                            uint32_t l0 = sn ? bl[1] : bl[0], l1 = sn ? bl[3] : bl[2];
                            MMA16816(d, ah[m], h0, h1);
                            MMA16816(d, ah[m], l0, l1);
                            MMA16816(d, al[m], h0, h1);
                        }
                }
            }
            if (c < NCHUNK - 1) sts_x(buf ^ 1);
            __syncthreads();
        }

        // epilogue
        const int g = l >> 2, tig = l & 3;
#pragma unroll
        for (int m = 0; m < 2; m++) {
            float pA = 0.0f, pB = 0.0f;
#pragma unroll
            for (int nf = 0; nf < 8; nf++)
#pragma unroll
                for (int e = 0; e < 2; e++) {
                    int col = wn * 64 + nf * 8 + 2 * tig + e;
                    pA += fast_tanh(acc[m][nf][e]     + bsm[col]) * usm[col];
                    pB += fast_tanh(acc[m][nf][2 + e] + bsm[col]) * usm[col];
                }
            pA += __shfl_xor_sync(0xffffffffu, pA, 1);
            pA += __shfl_xor_sync(0xffffffffu, pA, 2);
            pB += __shfl_xor_sync(0xffffffffu, pB, 1);
            pB += __shfl_xor_sync(0xffffffffu, pB, 2);
            if (tig == 0) {
                int row = wm * 32 + m * 16 + g;
                atomicAdd(&red[row], pA);          // 2 contributors/row
                atomicAdd(&red[row + 8], pB);
            }
        }
        __syncthreads();
        if (tid < TS) es[tid] = expf(red[tid]);    // faithful: no max-subtraction
        __syncthreads();

        if (tid < 64) red[tid] = es[tid] + es[tid + 64];
        __syncthreads();
        if (tid < 32) {
            float v = red[tid] + red[tid + 32];
#pragma unroll
            for (int off = 16; off > 0; off >>= 1)
                v += __shfl_down_sync(0xffffffffu, v, off);
            if (tid == 0) g_esum[b * NTILE + tile] = v;
        }
        float a0 = 0.f, a1 = 0.f, a2 = 0.f, a3 = 0.f;
#pragma unroll 4
        for (int s = 0; s < TS; s += 4) {
            a0 += es[s + 0] * xb[(size_t)(s + 0) * ND + tid];
            a1 += es[s + 1] * xb[(size_t)(s + 1) * ND + tid];
            a2 += es[s + 2] * xb[(size_t)(s + 2) * ND + tid];
            a3 += es[s + 3] * xb[(size_t)(s + 3) * ND + tid];
        }
        g_part[((size_t)b * NTILE + tile) * ND + tid] = (a0 + a1) + (a2 + a3);

    } else {
        // ===================== F path: exact fp32 FFMA2 =====================
        const int tx = tid & 15, ty = tid >> 4;
        float* bsm = (float*)(smem + F_BSM);
        float* usm = (float*)(smem + F_USM);
        float* es  = (float*)(smem + F_ES);
        float* red = (float*)(smem + F_XS(0));    // reuse x buf post-loop

        if (tid < NA) { bsm[tid] = bias[tid]; usm[tid] = u[tid]; }

        auto issue = [&](int buf, int k0) {
#pragma unroll
            for (int it = 0; it < 4; it++) {
                int t = tid + it * 256;
                int r = t >> 3, cc = (t & 7) << 2;
                cp16(smem + F_XS(buf) + (r * XSTR + cc) * 4,
                     (const char*)(xb + (size_t)r * ND + k0 + cc));
            }
#pragma unroll
            for (int it = 0; it < 4; it++) {
                int t = tid + it * 256;
                int r = t >> 5, cc = (t & 31) << 2;
                cp16(smem + F_WS(buf) + (r * NA + cc) * 4,
                     (const char*)(W + (size_t)(k0 + r) * NA + cc));
            }
            cp_commit();
        };

        unsigned long long acc[8][4];
#pragma unroll
        for (int i = 0; i < 8; i++)
#pragma unroll
            for (int p = 0; p < 4; p++) acc[i][p] = 0ull;

        issue(0, 0);

#pragma unroll 1
        for (int i = 0; i < NCHUNK; i++) {
            if (i < NCHUNK - 1) { issue((i + 1) & 1, (i + 1) * KC); cp_wait<1>(); }
            else cp_wait<0>();
            __syncthreads();

            const float* xc = (const float*)(smem + F_XS(i & 1));
            const float* wc = (const float*)(smem + F_WS(i & 1));
#pragma unroll
            for (int kk = 0; kk < KC; kk += 2) {
                float2 ax[8];
#pragma unroll
                for (int r = 0; r < 8; r++)
                    ax[r] = *(const float2*)(xc + (ty * 8 + r) * XSTR + kk);
#pragma unroll
                for (int sub = 0; sub < 2; sub++) {
                    unsigned long long bp[4];
#pragma unroll
                    for (int p = 0; p < 4; p++)
                        bp[p] = *(const unsigned long long*)(wc + (kk + sub) * NA + 2 * tx + 32 * p);
#pragma unroll
                    for (int r = 0; r < 8; r++) {
                        float a = sub ? ax[r].y : ax[r].x;
                        unsigned long long ap = pack2(a, a);
#pragma unroll
                        for (int p = 0; p < 4; p++) ffma2(acc[r][p], ap, bp[p]);
                    }
                }
            }
            __syncthreads();
        }

        // epilogue
#pragma unroll
        for (int r = 0; r < 8; r++) {
            float partial = 0.0f;
#pragma unroll
            for (int p = 0; p < 4; p++) {
                float lo, hi; unpack2(acc[r][p], lo, hi);
                int c0 = 2 * tx + 32 * p;
                partial += fast_tanh(lo + bsm[c0])     * usm[c0];
                partial += fast_tanh(hi + bsm[c0 + 1]) * usm[c0 + 1];
            }
            red[(ty * 8 + r) * 17 + tx] = partial;
        }
        __syncthreads();
        if (tid < TS) {
            float lg = 0.0f;
#pragma unroll
            for (int j = 0; j < 16; j++) lg += red[tid * 17 + j];
            es[tid] = expf(lg);                    // faithful: no max-subtraction
        }
        __syncthreads();

        if (tid < 64) red[tid] = es[tid] + es[tid + 64];
        __syncthreads();
        if (tid < 32) {
            float v = red[tid] + red[tid + 32];
#pragma unroll
            for (int off = 16; off > 0; off >>= 1)
                v += __shfl_down_sync(0xffffffffu, v, off);
            if (tid == 0) g_esum[b * NTILE + tile] = v;
        }
        float a0 = 0.f, a1 = 0.f, a2 = 0.f, a3 = 0.f;
#pragma unroll 4
        for (int s = 0; s < TS; s += 4) {
            a0 += es[s + 0] * xb[(size_t)(s + 0) * ND + tid];
            a1 += es[s + 1] * xb[(size_t)(s + 1) * ND + tid];
            a2 += es[s + 2] * xb[(size_t)(s + 2) * ND + tid];
            a3 += es[s + 3] * xb[(size_t)(s + 3) * ND + tid];
        }
        g_part[((size_t)b * NTILE + tile) * ND + tid] = (a0 + a1) + (a2 + a3);
    }
}

// ---------------------------------------------------------------------------
__global__ void __launch_bounds__(256) finish_kernel(float* __restrict__ out)
{
    const int b = blockIdx.x;
    const int tid = threadIdx.x;
    float s = 0.f;
#pragma unroll
    for (int t = 0; t < NTILE; t++) s += g_esum[b * NTILE + t];
    const float inv = 1.0f / (s + 1e-8f);
    float v = 0.f;
#pragma unroll
    for (int t = 0; t < NTILE; t++) v += g_part[((size_t)b * NTILE + t) * ND + tid];
    out[b * ND + tid] = v * inv;
}

extern "C" void kernel_launch(void* const* d_in, const int* in_sizes, int n_in,
                              void* d_out, int out_size) {
    const float* x    = (const float*)d_in[0];
    const float* W    = (const float*)d_in[1];
    const float* bias = (const float*)d_in[2];
    const float* u    = (const float*)d_in[3];
    float* out        = (float*)d_out;

    cudaFuncSetAttribute(scores_kernel, cudaFuncAttributeMaxDynamicSharedMemorySize, SMEM_TOTAL);

    wprep_kernel<<<(ND * NA + 255) / 256, 256>>>(W);
    scores_kernel<<<NB * NTILE, 256, SMEM_TOTAL>>>(x, W, bias, u);
    finish_kernel<<<NB, 256>>>(out);
}